// round 14
// baseline (speedup 1.0000x reference)
#include <cuda_runtime.h>
#include <cuda_fp16.h>
#include <math.h>

#define BQ 2
#define CQ 80
#define HQ 32
#define WQ 88
#define PIX (HQ * WQ)          // 2816 pixels
#define NPTS 262144            // 128*128*16 points per batch
#define PTS_PER_BLK 128
#define THREADS 320
#define NG8 10                 // 80 channels = 10 groups of 8 (uint4 of halves)
#define FROW 10                // feature row stride in uint4 (160B)
#define SROWU 64               // staging row stride in uints (256B, 0 mod 32 banks)

// Transposed features in fp16: (B, H*W, C), 8 channels per uint4, 10 uint4/pixel.
__device__ uint4 g_featTh[BQ * PIX * FROW];

// ---------------- prep: tiled transpose (B,C,HW) -> (B,HW,C) fp16 ----------------
__global__ void prep_kernel(const float* __restrict__ feat) {
    // Allow the dependent bev kernel to launch immediately; it waits (PDL)
    // before touching g_featTh.
    asm volatile("griddepcontrol.launch_dependents;");
    __shared__ float tile[32][33];
    int b = blockIdx.z;
    int ct = blockIdx.y * 32;
    int pt = blockIdx.x * 32;
    int tx = threadIdx.x, ty = threadIdx.y;   // (32,8)
    const float* src = feat + (size_t)b * CQ * PIX;
    #pragma unroll
    for (int j = 0; j < 32; j += 8) {
        int c = ct + ty + j;
        int p = pt + tx;
        if (c < CQ && p < PIX)
            tile[ty + j][tx] = src[(size_t)c * PIX + p];
    }
    __syncthreads();
    __half* dst = (__half*)g_featTh;
    dst += (size_t)b * PIX * CQ;
    #pragma unroll
    for (int j = 0; j < 32; j += 8) {
        int p = pt + ty + j;
        int c = ct + tx;
        if (c < CQ && p < PIX)
            dst[(size_t)p * CQ + c] = __float2half(tile[tx][ty + j]);
    }
}

// ---------------- main kernel ----------------
__global__ void __launch_bounds__(THREADS)
bev_kernel(float* __restrict__ out,
           const float* __restrict__ intrin,
           const float* __restrict__ extrin,
           const float* __restrict__ bda) {
    __shared__ uint4  s_wh[PTS_PER_BLK];                // 4 broadcast half2 weights
    __shared__ int4   s_idx4[PTS_PER_BLK];              // pixel * FROW (uint4 base)
    __shared__ uint4  s_stg[PTS_PER_BLK * (SROWU / 4)]; // 128 rows x 16 uint4 (fp16, swizzled)

    const int bidx = blockIdx.x;
    const int b = bidx >> 11;                 // 2048 blocks per batch
    const int nbase = (bidx & 2047) * PTS_PER_BLK;
    const int tid = threadIdx.x;

    // ---- Phase A: geometry for 128 points (independent of prep's output) ----
    if (tid < PTS_PER_BLK) {
        // Combined 3x4 matrix F = (intr*scale) * extr * bda, computed redundantly
        // per thread (reads are broadcast + cached; ~60 FMA).
        const float* In = intrin + b * 16;
        const float* Ex = extrin + b * 16;
        const float* Bd = bda + b * 16;
        float P[3][4], F[12];
        #pragma unroll
        for (int r = 0; r < 3; r++) {
            float s = (r < 2) ? 0.125f : 1.0f;
            #pragma unroll
            for (int cc = 0; cc < 4; cc++) {
                float acc = 0.0f;
                #pragma unroll
                for (int k = 0; k < 3; k++)
                    acc += __ldg(&In[r * 4 + k]) * s * __ldg(&Ex[k * 4 + cc]);
                P[r][cc] = acc;
            }
        }
        #pragma unroll
        for (int r = 0; r < 3; r++)
            #pragma unroll
            for (int cc = 0; cc < 4; cc++) {
                float acc = 0.0f;
                #pragma unroll
                for (int k = 0; k < 4; k++)
                    acc += P[r][k] * __ldg(&Bd[k * 4 + cc]);
                F[r * 4 + cc] = acc;
            }

        int n = nbase + tid;
        int ix = n >> 11;            // NY*NZ = 2048
        int iy = (n >> 4) & 127;     // NZ = 16
        int iz = n & 15;
        float X = -51.2f + ix * 0.8f;
        float Y = -51.2f + iy * 0.8f;
        float Z = -5.0f + iz * 0.5f;
        float px = F[0] * X + F[1] * Y + F[2]  * Z + F[3];
        float py = F[4] * X + F[5] * Y + F[6]  * Z + F[7];
        float pz = F[8] * X + F[9] * Y + F[10] * Z + F[11];
        float u = px / pz;
        float v = py / pz;
        u = u / (float)WQ * 2.0f - 1.0f;
        v = v / (float)HQ * 2.0f - 1.0f;
        float x = (u + 1.0f) * 0.5f * (float)(WQ - 1);
        float y = (v + 1.0f) * 0.5f * (float)(HQ - 1);
        if (!(isfinite(x) && isfinite(y))) { x = -10.0f; y = -10.0f; }
        float x0f = floorf(x), y0f = floorf(y);
        float wx1 = x - x0f, wy1 = y - y0f;
        float wx0 = 1.0f - wx1, wy0 = 1.0f - wy1;
        float x1f = x0f + 1.0f, y1f = y0f + 1.0f;
        bool vx0 = (x0f >= 0.0f) && (x0f <= (float)(WQ - 1));
        bool vx1 = (x1f >= 0.0f) && (x1f <= (float)(WQ - 1));
        bool vy0 = (y0f >= 0.0f) && (y0f <= (float)(HQ - 1));
        bool vy1 = (y1f >= 0.0f) && (y1f <= (float)(HQ - 1));
        int xi0 = (int)fminf(fmaxf(x0f, 0.0f), (float)(WQ - 1));
        int xi1 = (int)fminf(fmaxf(x1f, 0.0f), (float)(WQ - 1));
        int yi0 = (int)fminf(fmaxf(y0f, 0.0f), (float)(HQ - 1));
        int yi1 = (int)fminf(fmaxf(y1f, 0.0f), (float)(HQ - 1));
        int4 id;
        id.x = (yi0 * WQ + xi0) * FROW;
        id.y = (yi0 * WQ + xi1) * FROW;
        id.z = (yi1 * WQ + xi0) * FROW;
        id.w = (yi1 * WQ + xi1) * FROW;
        s_idx4[tid] = id;
        float w0 = (vx0 && vy0) ? wx0 * wy0 : 0.0f;
        float w1 = (vx1 && vy0) ? wx1 * wy0 : 0.0f;
        float w2 = (vx0 && vy1) ? wx0 * wy1 : 0.0f;
        float w3 = (vx1 && vy1) ? wx1 * wy1 : 0.0f;
        __half2 h0 = __float2half2_rn(w0);
        __half2 h1 = __float2half2_rn(w1);
        __half2 h2 = __float2half2_rn(w2);
        __half2 h3 = __float2half2_rn(w3);
        uint4 wh;
        wh.x = *reinterpret_cast<unsigned*>(&h0);
        wh.y = *reinterpret_cast<unsigned*>(&h1);
        wh.z = *reinterpret_cast<unsigned*>(&h2);
        wh.w = *reinterpret_cast<unsigned*>(&h3);
        s_wh[tid] = wh;
    }
    // PDL: wait for prep_kernel's writes to g_featTh to be complete+visible.
    asm volatile("griddepcontrol.wait;");
    __syncthreads();

    // ---- Phase B: predicated fp16 LDG.128 gathers (8 ch) + HFMA2 combine -> fp16 staging ----
    // Store word-rotated by rx = p4>>3 (0..3) so Phase C is conflict-free.
    const uint4* fT = g_featTh + (size_t)b * PIX * FROW;
    #pragma unroll
    for (int it = 0; it < 4; it++) {
        int i = it * THREADS + tid;   // 0..1279
        int p = i / NG8;
        int g = i - p * NG8;
        uint4 wh = s_wh[p];
        int4 id = s_idx4[p];
        __half2 acc0 = __float2half2_rn(0.f);
        __half2 acc1 = acc0, acc2 = acc0, acc3 = acc0;
        #define CORNER(WU, IDK)                                              \
            if (WU != 0u) {                                                  \
                uint4 raw = __ldg(&fT[IDK + g]);                             \
                __half2 wk = *reinterpret_cast<__half2*>(&WU);               \
                acc0 = __hfma2(wk, *reinterpret_cast<__half2*>(&raw.x), acc0); \
                acc1 = __hfma2(wk, *reinterpret_cast<__half2*>(&raw.y), acc1); \
                acc2 = __hfma2(wk, *reinterpret_cast<__half2*>(&raw.z), acc2); \
                acc3 = __hfma2(wk, *reinterpret_cast<__half2*>(&raw.w), acc3); \
            }
        CORNER(wh.x, id.x)
        CORNER(wh.y, id.y)
        CORNER(wh.z, id.z)
        CORNER(wh.w, id.w)
        #undef CORNER
        uint4 st;
        st.x = *reinterpret_cast<unsigned*>(&acc0);
        st.y = *reinterpret_cast<unsigned*>(&acc1);
        st.z = *reinterpret_cast<unsigned*>(&acc2);
        st.w = *reinterpret_cast<unsigned*>(&acc3);
        int p4 = p >> 2;
        int G = p4 & 7;
        int rx = p4 >> 3;             // 0..3: rotate words right by rx
        uint4 r = st;
        if (rx == 1) r = make_uint4(st.w, st.x, st.y, st.z);
        else if (rx == 2) r = make_uint4(st.z, st.w, st.x, st.y);
        else if (rx == 3) r = make_uint4(st.y, st.z, st.w, st.x);
        s_stg[p * (SROWU / 4) + (g ^ G)] = r;
    }
    __syncthreads();

    // ---- Phase C: conflict-free LDS.32 (half2 = channel pair) + 2x coalesced STG.128 ----
    {
        const unsigned* s_u = (const unsigned*)s_stg;
        float4* out4 = (float4*)out;
        #pragma unroll
        for (int it = 0; it < 4; it++) {
            int i = it * THREADS + tid;   // 0..1279
            int cp = i >> 5;              // channel-pair 0..39
            int p4 = i & 31;              // point-quad 0..31
            int G = p4 & 7;
            int rx = p4 >> 3;             // 0..3
            int word = 4 * ((cp >> 2) ^ G) + ((cp + rx) & 3);
            int base = (4 * p4) * SROWU + word;
            unsigned u0 = s_u[base + 0 * SROWU];
            unsigned u1 = s_u[base + 1 * SROWU];
            unsigned u2 = s_u[base + 2 * SROWU];
            unsigned u3 = s_u[base + 3 * SROWU];
            float2 f0 = __half22float2(*reinterpret_cast<__half2*>(&u0));
            float2 f1 = __half22float2(*reinterpret_cast<__half2*>(&u1));
            float2 f2 = __half22float2(*reinterpret_cast<__half2*>(&u2));
            float2 f3 = __half22float2(*reinterpret_cast<__half2*>(&u3));
            int c0 = 2 * cp;
            size_t idx0 = (size_t)(b * CQ + c0) * (NPTS / 4) + (nbase >> 2) + p4;
            size_t idx1 = idx0 + (NPTS / 4);
            out4[idx0] = make_float4(f0.x, f1.x, f2.x, f3.x);
            out4[idx1] = make_float4(f0.y, f1.y, f2.y, f3.y);
        }
    }
}

extern "C" void kernel_launch(void* const* d_in, const int* in_sizes, int n_in,
                              void* d_out, int out_size) {
    const float* img_feats = (const float*)d_in[0];
    const float* intrin    = (const float*)d_in[1];
    const float* extrin    = (const float*)d_in[2];
    const float* bda       = (const float*)d_in[3];
    float* out = (float*)d_out;

    dim3 tgrid((PIX + 31) / 32, (CQ + 31) / 32, BQ);
    prep_kernel<<<tgrid, dim3(32, 8)>>>(img_feats);

    int nblocks = BQ * (NPTS / PTS_PER_BLK);   // 4096
    cudaLaunchConfig_t cfg = {};
    cfg.gridDim = dim3(nblocks, 1, 1);
    cfg.blockDim = dim3(THREADS, 1, 1);
    cudaLaunchAttribute attrs[1];
    attrs[0].id = cudaLaunchAttributeProgrammaticStreamSerialization;
    attrs[0].val.programmaticStreamSerializationAllowed = 1;
    cfg.attrs = attrs;
    cfg.numAttrs = 1;
    cudaLaunchKernelEx(&cfg, bev_kernel, out, intrin, extrin, bda);
}

// round 15
// speedup vs baseline: 1.0484x; 1.0484x over previous
#include <cuda_runtime.h>
#include <cuda_fp16.h>
#include <math.h>

#define BQ 2
#define CQ 80
#define HQ 32
#define WQ 88
#define PIX (HQ * WQ)          // 2816 pixels
#define NPTS 262144            // 128*128*16 points per batch
#define PTS_PER_BLK 128
#define THREADS 320
#define NG8 10                 // 80 channels = 10 groups of 8 (uint4 of halves)
#define FROW 12                // feature row stride in uint4 (192B, padded from 160B)
#define SROWU 64               // staging row stride in uints (256B, 0 mod 32 banks)

// Transposed features in fp16: (B, H*W, Cpad), 8 channels per uint4, 12 uint4/pixel.
__device__ uint4 g_featTh[BQ * PIX * FROW];
// Combined 3x4 projection matrix per batch: F = (intr*scale) * extr * bda
__device__ float g_F[BQ][12];

static __device__ __forceinline__ unsigned h2bits(__half2 h) {
    return *reinterpret_cast<unsigned*>(&h);
}

// ---------------- prep: 32-pixel-column transpose (B,C,HW) -> (B,HW,Cpad) fp16 + matrices ----
// grid (PIX/32, BQ), 256 threads. Block loads 32 pixels x 80 channels coalesced,
// stores 320 uint4 (8 fp16 channels each) coalesced.
__global__ void __launch_bounds__(256)
prep_kernel(const float* __restrict__ feat,
            const float* __restrict__ intrin,
            const float* __restrict__ extrin,
            const float* __restrict__ bda) {
    __shared__ float tile[CQ][33];   // [channel][pixel_local], pad 33 vs 32
    int b = blockIdx.y;
    int pt = blockIdx.x * 32;
    int tid = threadIdx.x;

    if (blockIdx.x == 0 && blockIdx.y == 0 && tid < BQ) {
        int bb = tid;
        const float* In = intrin + bb * 16;
        const float* Ex = extrin + bb * 16;
        const float* Bd = bda + bb * 16;
        float P[3][4];
        for (int r = 0; r < 3; r++) {
            float s = (r < 2) ? 0.125f : 1.0f;
            for (int cc = 0; cc < 4; cc++) {
                float acc = 0.0f;
                for (int k = 0; k < 3; k++)
                    acc += In[r * 4 + k] * s * Ex[k * 4 + cc];
                P[r][cc] = acc;
            }
        }
        for (int r = 0; r < 3; r++)
            for (int cc = 0; cc < 4; cc++) {
                float acc = 0.0f;
                for (int k = 0; k < 4; k++)
                    acc += P[r][k] * Bd[k * 4 + cc];
                g_F[bb][r * 4 + cc] = acc;
            }
    }

    // Load: 80 channels x 32 pixels, fully coalesced (128B per warp-row).
    const float* src = feat + (size_t)b * CQ * PIX + pt;
    #pragma unroll
    for (int it = 0; it < (CQ * 32) / 256; it++) {   // 10
        int idx = it * 256 + tid;
        int c = idx >> 5;
        int lane = idx & 31;
        tile[c][lane] = src[(size_t)c * PIX + lane];
    }
    __syncthreads();

    // Store: 32 pixels x 10 uint4-groups = 320 items; pack 8 channels -> uint4.
    uint4* dst = g_featTh + (size_t)b * PIX * FROW;
    #pragma unroll
    for (int it = 0; it < 2; it++) {
        int j = it * 256 + tid;          // 0..511, valid < 320
        if (j < 32 * NG8) {
            int pix = j / NG8;
            int g = j - pix * NG8;
            int c0 = 8 * g;
            uint4 v;
            v.x = h2bits(__floats2half2_rn(tile[c0 + 0][pix], tile[c0 + 1][pix]));
            v.y = h2bits(__floats2half2_rn(tile[c0 + 2][pix], tile[c0 + 3][pix]));
            v.z = h2bits(__floats2half2_rn(tile[c0 + 4][pix], tile[c0 + 5][pix]));
            v.w = h2bits(__floats2half2_rn(tile[c0 + 6][pix], tile[c0 + 7][pix]));
            dst[(size_t)(pt + pix) * FROW + g] = v;
        }
    }
}

// ---------------- main kernel (bit-identical to the best-measured R9 variant) ----------------
__global__ void __launch_bounds__(THREADS)
bev_kernel(float* __restrict__ out) {
    __shared__ uint4  s_wh[PTS_PER_BLK];                // 4 broadcast half2 weights
    __shared__ int4   s_idx4[PTS_PER_BLK];              // pixel * FROW (uint4 base)
    __shared__ uint4  s_stg[PTS_PER_BLK * (SROWU / 4)]; // 128 rows x 16 uint4 (fp16, swizzled)

    const int bidx = blockIdx.x;
    const int b = bidx >> 11;                 // 2048 blocks per batch
    const int nbase = (bidx & 2047) * PTS_PER_BLK;
    const int tid = threadIdx.x;

    // ---- Phase A: geometry for 128 points ----
    if (tid < PTS_PER_BLK) {
        int n = nbase + tid;
        int ix = n >> 11;            // NY*NZ = 2048
        int iy = (n >> 4) & 127;     // NZ = 16
        int iz = n & 15;
        float X = -51.2f + ix * 0.8f;
        float Y = -51.2f + iy * 0.8f;
        float Z = -5.0f + iz * 0.5f;
        const float* F = g_F[b];
        float px = F[0] * X + F[1] * Y + F[2]  * Z + F[3];
        float py = F[4] * X + F[5] * Y + F[6]  * Z + F[7];
        float pz = F[8] * X + F[9] * Y + F[10] * Z + F[11];
        float u = px / pz;
        float v = py / pz;
        u = u / (float)WQ * 2.0f - 1.0f;
        v = v / (float)HQ * 2.0f - 1.0f;
        float x = (u + 1.0f) * 0.5f * (float)(WQ - 1);
        float y = (v + 1.0f) * 0.5f * (float)(HQ - 1);
        if (!(isfinite(x) && isfinite(y))) { x = -10.0f; y = -10.0f; }
        float x0f = floorf(x), y0f = floorf(y);
        float wx1 = x - x0f, wy1 = y - y0f;
        float wx0 = 1.0f - wx1, wy0 = 1.0f - wy1;
        float x1f = x0f + 1.0f, y1f = y0f + 1.0f;
        bool vx0 = (x0f >= 0.0f) && (x0f <= (float)(WQ - 1));
        bool vx1 = (x1f >= 0.0f) && (x1f <= (float)(WQ - 1));
        bool vy0 = (y0f >= 0.0f) && (y0f <= (float)(HQ - 1));
        bool vy1 = (y1f >= 0.0f) && (y1f <= (float)(HQ - 1));
        int xi0 = (int)fminf(fmaxf(x0f, 0.0f), (float)(WQ - 1));
        int xi1 = (int)fminf(fmaxf(x1f, 0.0f), (float)(WQ - 1));
        int yi0 = (int)fminf(fmaxf(y0f, 0.0f), (float)(HQ - 1));
        int yi1 = (int)fminf(fmaxf(y1f, 0.0f), (float)(HQ - 1));
        int4 id;
        id.x = (yi0 * WQ + xi0) * FROW;
        id.y = (yi0 * WQ + xi1) * FROW;
        id.z = (yi1 * WQ + xi0) * FROW;
        id.w = (yi1 * WQ + xi1) * FROW;
        s_idx4[tid] = id;
        float w0 = (vx0 && vy0) ? wx0 * wy0 : 0.0f;
        float w1 = (vx1 && vy0) ? wx1 * wy0 : 0.0f;
        float w2 = (vx0 && vy1) ? wx0 * wy1 : 0.0f;
        float w3 = (vx1 && vy1) ? wx1 * wy1 : 0.0f;
        __half2 h0 = __float2half2_rn(w0);
        __half2 h1 = __float2half2_rn(w1);
        __half2 h2 = __float2half2_rn(w2);
        __half2 h3 = __float2half2_rn(w3);
        uint4 wh;
        wh.x = h2bits(h0);
        wh.y = h2bits(h1);
        wh.z = h2bits(h2);
        wh.w = h2bits(h3);
        s_wh[tid] = wh;
    }
    __syncthreads();

    // ---- Phase B: predicated fp16 LDG.128 gathers (8 ch) + HFMA2 combine -> fp16 staging ----
    // Store word-rotated by rx = p4>>3 (0..3) so Phase C is conflict-free.
    const uint4* fT = g_featTh + (size_t)b * PIX * FROW;
    #pragma unroll
    for (int it = 0; it < 4; it++) {
        int i = it * THREADS + tid;   // 0..1279
        int p = i / NG8;
        int g = i - p * NG8;
        uint4 wh = s_wh[p];
        int4 id = s_idx4[p];
        __half2 acc0 = __float2half2_rn(0.f);
        __half2 acc1 = acc0, acc2 = acc0, acc3 = acc0;
        #define CORNER(WU, IDK)                                              \
            if (WU != 0u) {                                                  \
                uint4 raw = __ldg(&fT[IDK + g]);                             \
                __half2 wk = *reinterpret_cast<__half2*>(&WU);               \
                acc0 = __hfma2(wk, *reinterpret_cast<__half2*>(&raw.x), acc0); \
                acc1 = __hfma2(wk, *reinterpret_cast<__half2*>(&raw.y), acc1); \
                acc2 = __hfma2(wk, *reinterpret_cast<__half2*>(&raw.z), acc2); \
                acc3 = __hfma2(wk, *reinterpret_cast<__half2*>(&raw.w), acc3); \
            }
        CORNER(wh.x, id.x)
        CORNER(wh.y, id.y)
        CORNER(wh.z, id.z)
        CORNER(wh.w, id.w)
        #undef CORNER
        uint4 st;
        st.x = h2bits(acc0);
        st.y = h2bits(acc1);
        st.z = h2bits(acc2);
        st.w = h2bits(acc3);
        int p4 = p >> 2;
        int G = p4 & 7;
        int rx = p4 >> 3;             // 0..3: rotate words right by rx
        uint4 r = st;
        if (rx == 1) r = make_uint4(st.w, st.x, st.y, st.z);
        else if (rx == 2) r = make_uint4(st.z, st.w, st.x, st.y);
        else if (rx == 3) r = make_uint4(st.y, st.z, st.w, st.x);
        s_stg[p * (SROWU / 4) + (g ^ G)] = r;
    }
    __syncthreads();

    // ---- Phase C: conflict-free LDS.32 (half2 = channel pair) + 2x coalesced STG.128 ----
    {
        const unsigned* s_u = (const unsigned*)s_stg;
        float4* out4 = (float4*)out;
        #pragma unroll
        for (int it = 0; it < 4; it++) {
            int i = it * THREADS + tid;   // 0..1279
            int cp = i >> 5;              // channel-pair 0..39
            int p4 = i & 31;              // point-quad 0..31
            int G = p4 & 7;
            int rx = p4 >> 3;             // 0..3
            int word = 4 * ((cp >> 2) ^ G) + ((cp + rx) & 3);
            int base = (4 * p4) * SROWU + word;
            unsigned u0 = s_u[base + 0 * SROWU];
            unsigned u1 = s_u[base + 1 * SROWU];
            unsigned u2 = s_u[base + 2 * SROWU];
            unsigned u3 = s_u[base + 3 * SROWU];
            float2 f0 = __half22float2(*reinterpret_cast<__half2*>(&u0));
            float2 f1 = __half22float2(*reinterpret_cast<__half2*>(&u1));
            float2 f2 = __half22float2(*reinterpret_cast<__half2*>(&u2));
            float2 f3 = __half22float2(*reinterpret_cast<__half2*>(&u3));
            int c0 = 2 * cp;
            size_t idx0 = (size_t)(b * CQ + c0) * (NPTS / 4) + (nbase >> 2) + p4;
            size_t idx1 = idx0 + (NPTS / 4);
            out4[idx0] = make_float4(f0.x, f1.x, f2.x, f3.x);
            out4[idx1] = make_float4(f0.y, f1.y, f2.y, f3.y);
        }
    }
}

extern "C" void kernel_launch(void* const* d_in, const int* in_sizes, int n_in,
                              void* d_out, int out_size) {
    const float* img_feats = (const float*)d_in[0];
    const float* intrin    = (const float*)d_in[1];
    const float* extrin    = (const float*)d_in[2];
    const float* bda       = (const float*)d_in[3];
    float* out = (float*)d_out;

    dim3 pgrid(PIX / 32, BQ);
    prep_kernel<<<pgrid, 256>>>(img_feats, intrin, extrin, bda);

    int nblocks = BQ * (NPTS / PTS_PER_BLK);   // 4096
    bev_kernel<<<nblocks, THREADS>>>(out);
}